// round 1
// baseline (speedup 1.0000x reference)
#include <cuda_runtime.h>
#include <math.h>

// Problem constants: B=4, S=512, D=256
#define NB 4
#define NS 512
#define ND 256
#define NROWS (NB*NS)        // 2048
#define NPROJ (3*ND)         // 768

// ---------------- scratch (device globals; no allocation) ----------------
__device__ float g_Beff[ND*NPROJ];          // combined weight [K=256][N=768]
__device__ float g_biasN[NPROJ];            // 0 | b1 | bv
__device__ float g_proj[NROWS*NPROJ];       // hi | hj+b1 | values+bv  (6MB)
__device__ float g_scores[NB*NS*NS];        // scores -> attn in place (4MB)
__device__ float g_msg[NROWS*ND];           // message (2MB)
__device__ float g_preln[NROWS*ND];         // x + msg@Wo + bo (2MB)

// ---------------- weight packing ----------------
__global__ void pack_kernel(const float* __restrict__ W1, const float* __restrict__ Wv,
                            const float* __restrict__ b1, const float* __restrict__ bv) {
    int idx = blockIdx.x * blockDim.x + threadIdx.x;   // 0..196607
    int k = idx / NPROJ;
    int n = idx - k * NPROJ;
    float v;
    if (n < ND)            v = W1[k*ND + n] + W1[(2*ND + k)*ND + n];
    else if (n < 2*ND)     v = W1[(ND + k)*ND + (n - ND)] - W1[(2*ND + k)*ND + (n - ND)];
    else                   v = Wv[k*ND + (n - 2*ND)];
    g_Beff[idx] = v;
    if (idx < NPROJ) {
        float bb = 0.f;
        if (idx >= ND && idx < 2*ND) bb = b1[idx - ND];
        else if (idx >= 2*ND)        bb = bv[idx - 2*ND];
        g_biasN[idx] = bb;
    }
}

// ---------------- generic tiled fp32 GEMM: C = A@B (+bias[n]) (+res[m,n]) ---
// BM=BN=64, BK=16, 256 threads, 4x4 micro-tile. All dims divisible by tiles.
__global__ __launch_bounds__(256)
void sgemm_kernel(const float* __restrict__ A, int lda, long sA,
                  const float* __restrict__ Bm, int ldb, long sB,
                  float* __restrict__ C, int ldc, long sC,
                  int K,
                  const float* __restrict__ bias,
                  const float* __restrict__ res, int ldres) {
    __shared__ __align__(16) float As[16][68];
    __shared__ __align__(16) float Bs[16][64];
    long bz = blockIdx.z;
    A  += bz * sA;  Bm += bz * sB;  C += bz * sC;
    const int m0 = blockIdx.y * 64, n0 = blockIdx.x * 64;
    const int tid = threadIdx.x;
    const int tx = tid & 15, ty = tid >> 4;
    const int rA = tid >> 2, qA = tid & 3;     // A: 64 rows x 4 quads
    const int kB = tid >> 4, qB = tid & 15;    // B: 16 krows x 16 quads

    float acc[4][4] = {};
    for (int kk = 0; kk < K; kk += 16) {
        float4 a4 = *(const float4*)&A[(long)(m0 + rA)*lda + kk + qA*4];
        As[qA*4+0][rA] = a4.x; As[qA*4+1][rA] = a4.y;
        As[qA*4+2][rA] = a4.z; As[qA*4+3][rA] = a4.w;
        *(float4*)&Bs[kB][qB*4] = *(const float4*)&Bm[(long)(kk + kB)*ldb + n0 + qB*4];
        __syncthreads();
#pragma unroll
        for (int k = 0; k < 16; k++) {
            float4 av = *(const float4*)&As[k][ty*4];
            float4 bv4 = *(const float4*)&Bs[k][tx*4];
            float a[4] = {av.x, av.y, av.z, av.w};
            float b[4] = {bv4.x, bv4.y, bv4.z, bv4.w};
#pragma unroll
            for (int i = 0; i < 4; i++)
#pragma unroll
                for (int j = 0; j < 4; j++)
                    acc[i][j] = fmaf(a[i], b[j], acc[i][j]);
        }
        __syncthreads();
    }
#pragma unroll
    for (int i = 0; i < 4; i++) {
        int gm = m0 + ty*4 + i;
        float v[4];
#pragma unroll
        for (int j = 0; j < 4; j++) {
            int gn = n0 + tx*4 + j;
            float t = acc[i][j];
            if (bias) t += bias[gn];
            if (res)  t += res[(long)gm*ldres + gn];
            v[j] = t;
        }
        *(float4*)&C[(long)gm*ldc + n0 + tx*4] = make_float4(v[0], v[1], v[2], v[3]);
    }
}

// ---------------- pairwise relu-dot scores -------------------------------
// scores[b,i,j] = sum_h relu(hi[i,h] + hjb[j,h]) * w2[h] + b2
// 64x64 tile per block; only lower-triangular tiles (tj <= ti) launched.
__global__ __launch_bounds__(256)
void scores_kernel(const float* __restrict__ w2, const float* __restrict__ b2) {
    __shared__ __align__(16) float His[32][68];
    __shared__ __align__(16) float Hjs[32][68];
    __shared__ float w2s[ND];
    const int b = blockIdx.y;
    const int t = blockIdx.x;
    int ti = (int)((sqrtf(8.f*t + 1.f) - 1.f) * 0.5f);
    while ((ti + 1)*(ti + 2)/2 <= t) ti++;
    while (ti*(ti + 1)/2 > t) ti--;
    const int tj = t - ti*(ti + 1)/2;
    const int i0 = ti * 64, j0 = tj * 64;
    const int tid = threadIdx.x;
    w2s[tid] = w2[tid];
    const int tx = tid & 15, ty = tid >> 4;
    const float* hiBase = g_proj + (long)(b*NS + i0) * NPROJ;         // hi cols
    const float* hjBase = g_proj + (long)(b*NS + j0) * NPROJ + ND;    // hj+b1 cols
    const float b2v = b2[0];

    float acc[4][4] = {};
    for (int kk = 0; kk < ND; kk += 32) {
#pragma unroll
        for (int l = 0; l < 2; l++) {
            int idx = l*256 + tid;          // 0..511
            int r  = idx >> 3;              // row 0..63
            int qq = idx & 7;               // k-quad 0..7
            float4 va = *(const float4*)&hiBase[(long)r*NPROJ + kk + qq*4];
            His[qq*4+0][r] = va.x; His[qq*4+1][r] = va.y;
            His[qq*4+2][r] = va.z; His[qq*4+3][r] = va.w;
            float4 vb = *(const float4*)&hjBase[(long)r*NPROJ + kk + qq*4];
            Hjs[qq*4+0][r] = vb.x; Hjs[qq*4+1][r] = vb.y;
            Hjs[qq*4+2][r] = vb.z; Hjs[qq*4+3][r] = vb.w;
        }
        __syncthreads();
#pragma unroll
        for (int k = 0; k < 32; k++) {
            float4 av = *(const float4*)&His[k][ty*4];
            float4 bv4 = *(const float4*)&Hjs[k][tx*4];
            float w = w2s[kk + k];
            float a[4] = {av.x, av.y, av.z, av.w};
            float bb[4] = {bv4.x, bv4.y, bv4.z, bv4.w};
#pragma unroll
            for (int i = 0; i < 4; i++)
#pragma unroll
                for (int j = 0; j < 4; j++)
                    acc[i][j] = fmaf(fmaxf(a[i] + bb[j], 0.f), w, acc[i][j]);
        }
        __syncthreads();
    }
    float* out = g_scores + (long)b * NS * NS;
#pragma unroll
    for (int i = 0; i < 4; i++) {
        int gi = i0 + ty*4 + i;
        float4 o = make_float4(acc[i][0]+b2v, acc[i][1]+b2v, acc[i][2]+b2v, acc[i][3]+b2v);
        *(float4*)&out[(long)gi*NS + j0 + tx*4] = o;
    }
}

// ---------------- masked softmax (in place; zeros for j>=i and row i=0) ---
__global__ __launch_bounds__(256)
void softmax_kernel() {
    const int row = blockIdx.x;           // b*512 + i
    const int i = row & (NS - 1);
    float* s = g_scores + (long)row * NS;
    const int tid = threadIdx.x;
    __shared__ float red[256];
    if (i == 0) { s[tid] = 0.f; s[tid + 256] = 0.f; return; }
    float v0 = (tid       < i) ? s[tid]       : -3.0e38f;
    float v1 = (tid + 256 < i) ? s[tid + 256] : -3.0e38f;
    red[tid] = fmaxf(v0, v1);
    __syncthreads();
#pragma unroll
    for (int off = 128; off > 0; off >>= 1) {
        if (tid < off) red[tid] = fmaxf(red[tid], red[tid + off]);
        __syncthreads();
    }
    float m = red[0];
    __syncthreads();
    float e0 = (tid       < i) ? __expf(v0 - m) : 0.f;
    float e1 = (tid + 256 < i) ? __expf(v1 - m) : 0.f;
    red[tid] = e0 + e1;
    __syncthreads();
#pragma unroll
    for (int off = 128; off > 0; off >>= 1) {
        if (tid < off) red[tid] += red[tid + off];
        __syncthreads();
    }
    float inv = 1.f / red[0];
    s[tid]       = e0 * inv;
    s[tid + 256] = e1 * inv;
}

// ---------------- layernorm -> d_out --------------------------------------
__global__ __launch_bounds__(256)
void ln_kernel(const float* __restrict__ gamma, const float* __restrict__ beta,
               float* __restrict__ out) {
    const int row = blockIdx.x;
    const int tid = threadIdx.x;
    __shared__ float red[256];
    float v = g_preln[(long)row*ND + tid];
    red[tid] = v;
    __syncthreads();
#pragma unroll
    for (int off = 128; off > 0; off >>= 1) {
        if (tid < off) red[tid] += red[tid + off];
        __syncthreads();
    }
    float mu = red[0] * (1.f / ND);
    __syncthreads();
    float d = v - mu;
    red[tid] = d * d;
    __syncthreads();
#pragma unroll
    for (int off = 128; off > 0; off >>= 1) {
        if (tid < off) red[tid] += red[tid + off];
        __syncthreads();
    }
    float var = red[0] * (1.f / ND);
    float r = rsqrtf(var + 1e-5f);
    out[(long)row*ND + tid] = d * r * gamma[tid] + beta[tid];
}

// ---------------- launch ---------------------------------------------------
extern "C" void kernel_launch(void* const* d_in, const int* in_sizes, int n_in,
                              void* d_out, int out_size) {
    const float* x     = (const float*)d_in[0];
    const float* W1    = (const float*)d_in[1];
    const float* b1    = (const float*)d_in[2];
    const float* w2    = (const float*)d_in[3];
    const float* b2    = (const float*)d_in[4];
    const float* Wv    = (const float*)d_in[5];
    const float* bv    = (const float*)d_in[6];
    const float* Wo    = (const float*)d_in[7];
    const float* bo    = (const float*)d_in[8];
    const float* gamma = (const float*)d_in[9];
    const float* beta  = (const float*)d_in[10];
    float* out = (float*)d_out;

    static float *pBeff = nullptr, *pBiasN = nullptr, *pProj = nullptr,
                 *pScores = nullptr, *pMsg = nullptr, *pPre = nullptr;
    if (!pBeff) {   // pure symbol lookups, cached before capture (no alloc, no stream ops)
        cudaGetSymbolAddress((void**)&pBeff,   g_Beff);
        cudaGetSymbolAddress((void**)&pBiasN,  g_biasN);
        cudaGetSymbolAddress((void**)&pProj,   g_proj);
        cudaGetSymbolAddress((void**)&pScores, g_scores);
        cudaGetSymbolAddress((void**)&pMsg,    g_msg);
        cudaGetSymbolAddress((void**)&pPre,    g_preln);
    }

    // 1. pack combined weights + bias vector
    pack_kernel<<<(ND*NPROJ)/256, 256>>>(W1, Wv, b1, bv);

    // 2. fused projection GEMM: proj[2048,768] = x @ Beff (+ biasN)
    sgemm_kernel<<<dim3(NPROJ/64, NROWS/64, 1), 256>>>(
        x, ND, 0, pBeff, NPROJ, 0, pProj, NPROJ, 0, ND, pBiasN, nullptr, 0);

    // 3. pairwise relu-dot scores (lower-tri tiles only)
    scores_kernel<<<dim3(36, NB), 256>>>(w2, b2);

    // 4. masked softmax (writes zeros in masked region -> next GEMM unmasked)
    softmax_kernel<<<NROWS, 256>>>();

    // 5. message = attn @ values (batched)
    sgemm_kernel<<<dim3(ND/64, NS/64, NB), 256>>>(
        pScores, NS, (long)NS*NS,
        pProj + 2*ND, NPROJ, (long)NS*NPROJ,
        pMsg, ND, (long)NS*ND,
        NS, nullptr, nullptr, 0);

    // 6. out = msg @ Wo + bo + x
    sgemm_kernel<<<dim3(ND/64, NROWS/64, 1), 256>>>(
        pMsg, ND, 0, Wo, ND, 0, pPre, ND, 0, ND, bo, x, ND);

    // 7. layernorm -> d_out
    ln_kernel<<<NROWS, 256>>>(gamma, beta, out);
}

// round 2
// speedup vs baseline: 1.0434x; 1.0434x over previous
#include <cuda_runtime.h>
#include <math.h>

// Problem constants: B=4, S=512, D=256
#define NB 4
#define NS 512
#define ND 256
#define NROWS (NB*NS)        // 2048
#define NPROJ (3*ND)         // 768

typedef unsigned long long ull;

// ---------------- f32x2 packed helpers ----------------
__device__ __forceinline__ ull pk2(float x, float y) {
    ull r; asm("mov.b64 %0, {%1, %2};" : "=l"(r) : "f"(x), "f"(y)); return r;
}
__device__ __forceinline__ void up2(ull v, float& x, float& y) {
    asm("mov.b64 {%0, %1}, %2;" : "=f"(x), "=f"(y) : "l"(v));
}
__device__ __forceinline__ ull fma2(ull a, ull b, ull c) {
    ull d; asm("fma.rn.f32x2 %0, %1, %2, %3;" : "=l"(d) : "l"(a), "l"(b), "l"(c)); return d;
}
__device__ __forceinline__ ull add2(ull a, ull b) {
    ull d; asm("add.rn.f32x2 %0, %1, %2;" : "=l"(d) : "l"(a), "l"(b)); return d;
}

// ---------------- scratch (device globals; no allocation) ----------------
__device__ float g_Beff[ND*NPROJ];          // combined weight [K=256][N=768]
__device__ float g_biasN[NPROJ];            // 0 | b1 | bv
__device__ float g_proj[NROWS*NPROJ];       // hi | hj+b1 | values+bv  (6MB)
__device__ float g_scores[NB*NS*NS];        // scores -> attn in place (4MB)
__device__ float g_msg[NROWS*ND];           // message (2MB)
__device__ float g_preln[NROWS*ND];         // x + msg@Wo + bo (2MB)

// ---------------- weight packing ----------------
__global__ void pack_kernel(const float* __restrict__ W1, const float* __restrict__ Wv,
                            const float* __restrict__ b1, const float* __restrict__ bv) {
    int idx = blockIdx.x * blockDim.x + threadIdx.x;   // 0..196607
    int k = idx / NPROJ;
    int n = idx - k * NPROJ;
    float v;
    if (n < ND)            v = W1[k*ND + n] + W1[(2*ND + k)*ND + n];
    else if (n < 2*ND)     v = W1[(ND + k)*ND + (n - ND)] - W1[(2*ND + k)*ND + (n - ND)];
    else                   v = Wv[k*ND + (n - 2*ND)];
    g_Beff[idx] = v;
    if (idx < NPROJ) {
        float bb = 0.f;
        if (idx >= ND && idx < 2*ND) bb = b1[idx - ND];
        else if (idx >= 2*ND)        bb = bv[idx - 2*ND];
        g_biasN[idx] = bb;
    }
}

// ---------------- tiled fp32 GEMM with packed f32x2 inner loop ------------
// C = A@B (+bias[n]) (+res[m,n]); BM=BN=64, BK=16, 256 threads, 4x4 micro-tile.
// causal!=0 limits K to m0+64 (attn rows are strictly lower-triangular).
__global__ __launch_bounds__(256)
void sgemm_kernel(const float* __restrict__ A, int lda, long sA,
                  const float* __restrict__ Bm, int ldb, long sB,
                  float* __restrict__ C, int ldc, long sC,
                  int K, int causal,
                  const float* __restrict__ bias,
                  const float* __restrict__ res, int ldres) {
    __shared__ __align__(16) float As[16][68];   // [k][i] — i contiguous
    __shared__ __align__(16) float Bs[16][64];   // [k][j]
    long bz = blockIdx.z;
    A  += bz * sA;  Bm += bz * sB;  C += bz * sC;
    const int m0 = blockIdx.y * 64, n0 = blockIdx.x * 64;
    const int Keff = causal ? (m0 + 64) : K;
    const int tid = threadIdx.x;
    const int tx = tid & 15, ty = tid >> 4;
    const int rA = tid >> 2, qA = tid & 3;     // A: 64 rows x 4 quads
    const int kB = tid >> 4, qB = tid & 15;    // B: 16 krows x 16 quads

    ull acc2[2][4];
#pragma unroll
    for (int p = 0; p < 2; p++)
#pragma unroll
        for (int j = 0; j < 4; j++) acc2[p][j] = 0ULL;

    for (int kk = 0; kk < Keff; kk += 16) {
        float4 a4 = *(const float4*)&A[(long)(m0 + rA)*lda + kk + qA*4];
        As[qA*4+0][rA] = a4.x; As[qA*4+1][rA] = a4.y;
        As[qA*4+2][rA] = a4.z; As[qA*4+3][rA] = a4.w;
        *(float4*)&Bs[kB][qB*4] = *(const float4*)&Bm[(long)(kk + kB)*ldb + n0 + qB*4];
        __syncthreads();
#pragma unroll
        for (int k = 0; k < 16; k++) {
            ull a01 = *(const ull*)&As[k][ty*4];       // rows ty*4, ty*4+1
            ull a23 = *(const ull*)&As[k][ty*4+2];     // rows ty*4+2, ty*4+3
            float4 b4 = *(const float4*)&Bs[k][tx*4];
            ull b0 = pk2(b4.x, b4.x), b1p = pk2(b4.y, b4.y);
            ull b2p = pk2(b4.z, b4.z), b3p = pk2(b4.w, b4.w);
            acc2[0][0] = fma2(a01, b0,  acc2[0][0]);
            acc2[0][1] = fma2(a01, b1p, acc2[0][1]);
            acc2[0][2] = fma2(a01, b2p, acc2[0][2]);
            acc2[0][3] = fma2(a01, b3p, acc2[0][3]);
            acc2[1][0] = fma2(a23, b0,  acc2[1][0]);
            acc2[1][1] = fma2(a23, b1p, acc2[1][1]);
            acc2[1][2] = fma2(a23, b2p, acc2[1][2]);
            acc2[1][3] = fma2(a23, b3p, acc2[1][3]);
        }
        __syncthreads();
    }
    float acc[4][4];
#pragma unroll
    for (int p = 0; p < 2; p++)
#pragma unroll
        for (int j = 0; j < 4; j++)
            up2(acc2[p][j], acc[2*p][j], acc[2*p+1][j]);
#pragma unroll
    for (int i = 0; i < 4; i++) {
        int gm = m0 + ty*4 + i;
        float v[4];
#pragma unroll
        for (int j = 0; j < 4; j++) {
            int gn = n0 + tx*4 + j;
            float t = acc[i][j];
            if (bias) t += bias[gn];
            if (res)  t += res[(long)gm*ldres + gn];
            v[j] = t;
        }
        *(float4*)&C[(long)gm*ldc + n0 + tx*4] = make_float4(v[0], v[1], v[2], v[3]);
    }
}

// ---------------- pairwise relu-dot scores (packed f32x2) -----------------
// scores[b,i,j] = sum_h relu(hi[i,h] + hjb[j,h]) * w2[h] + b2
// relu(x)*w == (x + |x|) * (0.5*w)  exactly.
__global__ __launch_bounds__(256)
void scores_kernel(const float* __restrict__ w2, const float* __restrict__ b2) {
    __shared__ __align__(16) float His[32][68];
    __shared__ __align__(16) float Hjs[32][68];
    __shared__ float w2s[ND];
    const int b = blockIdx.y;
    const int t = blockIdx.x;
    int ti = (int)((sqrtf(8.f*t + 1.f) - 1.f) * 0.5f);
    while ((ti + 1)*(ti + 2)/2 <= t) ti++;
    while (ti*(ti + 1)/2 > t) ti--;
    const int tj = t - ti*(ti + 1)/2;
    const int i0 = ti * 64, j0 = tj * 64;
    const int tid = threadIdx.x;
    w2s[tid] = w2[tid];
    const int tx = tid & 15, ty = tid >> 4;
    const float* hiBase = g_proj + (long)(b*NS + i0) * NPROJ;         // hi cols
    const float* hjBase = g_proj + (long)(b*NS + j0) * NPROJ + ND;    // hj+b1 cols
    const float b2v = b2[0];
    const ull ABS2 = 0x7FFFFFFF7FFFFFFFULL;

    ull acc2[2][4];
#pragma unroll
    for (int p = 0; p < 2; p++)
#pragma unroll
        for (int j = 0; j < 4; j++) acc2[p][j] = 0ULL;

    for (int kk = 0; kk < ND; kk += 32) {
#pragma unroll
        for (int l = 0; l < 2; l++) {
            int idx = l*256 + tid;          // 0..511
            int r  = idx >> 3;              // row 0..63
            int qq = idx & 7;               // k-quad 0..7
            float4 va = *(const float4*)&hiBase[(long)r*NPROJ + kk + qq*4];
            His[qq*4+0][r] = va.x; His[qq*4+1][r] = va.y;
            His[qq*4+2][r] = va.z; His[qq*4+3][r] = va.w;
            float4 vb = *(const float4*)&hjBase[(long)r*NPROJ + kk + qq*4];
            Hjs[qq*4+0][r] = vb.x; Hjs[qq*4+1][r] = vb.y;
            Hjs[qq*4+2][r] = vb.z; Hjs[qq*4+3][r] = vb.w;
        }
        __syncthreads();
#pragma unroll
        for (int k = 0; k < 32; k++) {
            ull a01 = *(const ull*)&His[k][ty*4];
            ull a23 = *(const ull*)&His[k][ty*4+2];
            float4 h4 = *(const float4*)&Hjs[k][tx*4];
            float wh = 0.5f * w2s[kk + k];
            ull hw = pk2(wh, wh);
            ull bj[4] = { pk2(h4.x, h4.x), pk2(h4.y, h4.y),
                          pk2(h4.z, h4.z), pk2(h4.w, h4.w) };
#pragma unroll
            for (int j = 0; j < 4; j++) {
                ull t0 = add2(a01, bj[j]);
                ull u0 = add2(t0, t0 & ABS2);         // x + |x| = 2*relu(x)
                acc2[0][j] = fma2(u0, hw, acc2[0][j]);
                ull t1 = add2(a23, bj[j]);
                ull u1 = add2(t1, t1 & ABS2);
                acc2[1][j] = fma2(u1, hw, acc2[1][j]);
            }
        }
        __syncthreads();
    }
    float acc[4][4];
#pragma unroll
    for (int p = 0; p < 2; p++)
#pragma unroll
        for (int j = 0; j < 4; j++)
            up2(acc2[p][j], acc[2*p][j], acc[2*p+1][j]);
    float* out = g_scores + (long)b * NS * NS;
#pragma unroll
    for (int i = 0; i < 4; i++) {
        int gi = i0 + ty*4 + i;
        float4 o = make_float4(acc[i][0]+b2v, acc[i][1]+b2v, acc[i][2]+b2v, acc[i][3]+b2v);
        *(float4*)&out[(long)gi*NS + j0 + tx*4] = o;
    }
}

// ---------------- masked softmax (128 thr/row, shuffle reductions) --------
__global__ __launch_bounds__(128)
void softmax_kernel() {
    const int row = blockIdx.x;           // b*512 + i
    const int i = row & (NS - 1);
    float4* s4 = (float4*)(g_scores + (long)row * NS);
    const int tid = threadIdx.x;
    if (i == 0) { s4[tid] = make_float4(0.f, 0.f, 0.f, 0.f); return; }
    const int lane = tid & 31, warp = tid >> 5;
    const int base = tid * 4;
    float4 v = s4[tid];
    float va = (base + 0 < i) ? v.x : -3.0e38f;
    float vb = (base + 1 < i) ? v.y : -3.0e38f;
    float vc = (base + 2 < i) ? v.z : -3.0e38f;
    float vd = (base + 3 < i) ? v.w : -3.0e38f;
    float m = fmaxf(fmaxf(va, vb), fmaxf(vc, vd));
#pragma unroll
    for (int off = 16; off > 0; off >>= 1)
        m = fmaxf(m, __shfl_xor_sync(0xffffffffu, m, off));
    __shared__ float smax[4], ssum[4];
    if (lane == 0) smax[warp] = m;
    __syncthreads();
    m = fmaxf(fmaxf(smax[0], smax[1]), fmaxf(smax[2], smax[3]));
    float e0 = (base + 0 < i) ? __expf(va - m) : 0.f;
    float e1 = (base + 1 < i) ? __expf(vb - m) : 0.f;
    float e2 = (base + 2 < i) ? __expf(vc - m) : 0.f;
    float e3 = (base + 3 < i) ? __expf(vd - m) : 0.f;
    float sum = (e0 + e1) + (e2 + e3);
#pragma unroll
    for (int off = 16; off > 0; off >>= 1)
        sum += __shfl_xor_sync(0xffffffffu, sum, off);
    if (lane == 0) ssum[warp] = sum;
    __syncthreads();
    sum = (ssum[0] + ssum[1]) + (ssum[2] + ssum[3]);
    float inv = 1.f / sum;
    s4[tid] = make_float4(e0*inv, e1*inv, e2*inv, e3*inv);
}

// ---------------- layernorm -> d_out (shuffle reductions) -----------------
__global__ __launch_bounds__(256)
void ln_kernel(const float* __restrict__ gamma, const float* __restrict__ beta,
               float* __restrict__ out) {
    const int row = blockIdx.x;
    const int tid = threadIdx.x;
    const int lane = tid & 31, warp = tid >> 5;
    __shared__ float r1[8], r2[8];
    float v = g_preln[(long)row*ND + tid];
    float s = v;
#pragma unroll
    for (int off = 16; off > 0; off >>= 1)
        s += __shfl_xor_sync(0xffffffffu, s, off);
    if (lane == 0) r1[warp] = s;
    __syncthreads();
    float tot = 0.f;
#pragma unroll
    for (int w = 0; w < 8; w++) tot += r1[w];
    float mu = tot * (1.f / ND);
    float d = v - mu;
    float q = d * d;
#pragma unroll
    for (int off = 16; off > 0; off >>= 1)
        q += __shfl_xor_sync(0xffffffffu, q, off);
    if (lane == 0) r2[warp] = q;
    __syncthreads();
    float var = 0.f;
#pragma unroll
    for (int w = 0; w < 8; w++) var += r2[w];
    var *= (1.f / ND);
    float r = rsqrtf(var + 1e-5f);
    out[(long)row*ND + tid] = d * r * gamma[tid] + beta[tid];
}

// ---------------- launch ---------------------------------------------------
extern "C" void kernel_launch(void* const* d_in, const int* in_sizes, int n_in,
                              void* d_out, int out_size) {
    const float* x     = (const float*)d_in[0];
    const float* W1    = (const float*)d_in[1];
    const float* b1    = (const float*)d_in[2];
    const float* w2    = (const float*)d_in[3];
    const float* b2    = (const float*)d_in[4];
    const float* Wv    = (const float*)d_in[5];
    const float* bv    = (const float*)d_in[6];
    const float* Wo    = (const float*)d_in[7];
    const float* bo    = (const float*)d_in[8];
    const float* gamma = (const float*)d_in[9];
    const float* beta  = (const float*)d_in[10];
    float* out = (float*)d_out;

    static float *pBeff = nullptr, *pBiasN = nullptr, *pProj = nullptr,
                 *pScores = nullptr, *pMsg = nullptr, *pPre = nullptr;
    if (!pBeff) {   // pure symbol lookups, cached before capture (no alloc, no stream ops)
        cudaGetSymbolAddress((void**)&pBeff,   g_Beff);
        cudaGetSymbolAddress((void**)&pBiasN,  g_biasN);
        cudaGetSymbolAddress((void**)&pProj,   g_proj);
        cudaGetSymbolAddress((void**)&pScores, g_scores);
        cudaGetSymbolAddress((void**)&pMsg,    g_msg);
        cudaGetSymbolAddress((void**)&pPre,    g_preln);
    }

    // 1. pack combined weights + bias vector
    pack_kernel<<<(ND*NPROJ)/256, 256>>>(W1, Wv, b1, bv);

    // 2. fused projection GEMM: proj[2048,768] = x @ Beff (+ biasN)
    sgemm_kernel<<<dim3(NPROJ/64, NROWS/64, 1), 256>>>(
        x, ND, 0, pBeff, NPROJ, 0, pProj, NPROJ, 0, ND, 0, pBiasN, nullptr, 0);

    // 3. pairwise relu-dot scores (lower-tri tiles only)
    scores_kernel<<<dim3(36, NB), 256>>>(w2, b2);

    // 4. masked softmax (writes zeros in masked region -> next GEMM unmasked)
    softmax_kernel<<<NROWS, 128>>>();

    // 5. message = attn @ values (batched, causal K-trim: attn cols >= m0+64 are 0)
    sgemm_kernel<<<dim3(ND/64, NS/64, NB), 256>>>(
        pScores, NS, (long)NS*NS,
        pProj + 2*ND, NPROJ, (long)NS*NPROJ,
        pMsg, ND, (long)NS*ND,
        NS, 1, nullptr, nullptr, 0);

    // 6. out = msg @ Wo + bo + x
    sgemm_kernel<<<dim3(ND/64, NROWS/64, 1), 256>>>(
        pMsg, ND, 0, Wo, ND, 0, pPre, ND, 0, ND, 0, bo, x, ND);

    // 7. layernorm -> d_out
    ln_kernel<<<NROWS, 256>>>(gamma, beta, out);
}